// round 9
// baseline (speedup 1.0000x reference)
#include <cuda_runtime.h>
#include <cstdint>

// GestureRNN: 2-layer ReLU RNN, B=4096, T=512, IN=10, H=32, NCLS=9.
// R9 "scheme D": 2 warps per batch (each owns 16 output units), and the
// 32-term k-sum split across lane halves (ks = lid>>4). Per-lane weight
// rows halve (24 ull) -> ~90 regs -> 20 warps/SM. Partials merged with a
// single shfl.xor(16); ONE __syncthreads per timestep (both h1_{t+1} and
// h2_t depend only on h1_t, h2_{t-1}, so one publish phase suffices).
// Parity double-buffered state; x slices prefetched one step ahead.

typedef unsigned long long ull;

__device__ __forceinline__ ull ffma2(ull a, ull b, ull c) {
    ull d;
    asm("fma.rn.f32x2 %0, %1, %2, %3;" : "=l"(d) : "l"(a), "l"(b), "l"(c));
    return d;
}
__device__ __forceinline__ ull fadd2(ull a, ull b) {
    ull d;
    asm("add.rn.f32x2 %0, %1, %2;" : "=l"(d) : "l"(a), "l"(b));
    return d;
}
__device__ __forceinline__ float hsum2(ull a) {
    return __uint_as_float((unsigned)a) + __uint_as_float((unsigned)(a >> 32));
}

static constexpr int T_STEPS = 512;
static constexpr int BATCH   = 4096;
static constexpr int IN_DIM  = 10;
static constexpr int NCLS    = 9;

// CTA: 128 threads = 4 warps = 2 batches (warp pair per batch).
__global__ void __launch_bounds__(128, 5) rnn_fused_kernel(
    const float* __restrict__ x,
    const float* __restrict__ Wih0, const float* __restrict__ Whh0,
    const float* __restrict__ bih0, const float* __restrict__ bhh0,
    const float* __restrict__ Wih1, const float* __restrict__ Whh1,
    const float* __restrict__ bih1, const float* __restrict__ bhh1,
    const float* __restrict__ Wfc,  const float* __restrict__ bfc,
    float* __restrict__ out)
{
    __shared__ float sH1[2][2][32];   // [batch-in-CTA][parity][unit]
    __shared__ float sH2[2][2][32];

    const int tid = threadIdx.x;
    const int wi  = tid >> 5;          // warp in CTA: 0..3
    const int lid = tid & 31;
    const int bb  = wi >> 1;           // batch-in-CTA: 0,1
    const int hb  = wi & 1;            // unit-half: 0 -> units 0-15, 1 -> 16-31
    const int ks  = lid >> 4;          // k-half: 0 -> k 0-15, 1 -> k 16-31
    const int ul  = lid & 15;
    const int u   = hb * 16 + ul;      // owned output unit
    const int b   = blockIdx.x * 2 + bb;

    // ---- per-lane weights: row u, k-half ks, packed f32x2 ----
    ull w0h[8], wi1h[8], wh1h[8];
    {
        const ulonglong2* a = (const ulonglong2*)(Whh0 + u * 32 + ks * 16);
        const ulonglong2* c = (const ulonglong2*)(Wih1 + u * 32 + ks * 16);
        const ulonglong2* d = (const ulonglong2*)(Whh1 + u * 32 + ks * 16);
#pragma unroll
        for (int m = 0; m < 4; m++) {
            ulonglong2 v;
            v = a[m]; w0h[2*m]  = v.x; w0h[2*m+1]  = v.y;
            v = c[m]; wi1h[2*m] = v.x; wi1h[2*m+1] = v.y;
            v = d[m]; wh1h[2*m] = v.x; wh1h[2*m+1] = v.y;
        }
    }
    // input-projection slice: ks=0 -> i in [0,6) (3 ull), ks=1 -> [6,10) (2 ull)
    ull xw[3];
    {
        const ull* p = (const ull*)(Wih0 + u * IN_DIM + ks * 6);
        xw[0] = p[0]; xw[1] = p[1]; xw[2] = ks ? 0ull : p[2];
    }
    const float bsel = ks ? (bih1[u] + bhh1[u]) : (bih0[u] + bhh0[u]);
    const float b0u  = bih0[u] + bhh0[u];   // needed by ks=0 path only (== bsel)
    (void)b0u;

    const float* xb = x + (size_t)b * (T_STEPS * IN_DIM) + ks * 6;

    // hoisted pointers
    const ulonglong2* h1r[2] = {
        (const ulonglong2*)sH1[bb][0] + ks * 4,
        (const ulonglong2*)sH1[bb][1] + ks * 4 };
    const ulonglong2* h2r[2] = {
        (const ulonglong2*)sH2[bb][0] + ks * 4,
        (const ulonglong2*)sH2[bb][1] + ks * 4 };
    float* st[2] = {
        (ks ? sH2[bb][0] : sH1[bb][0]) + u,
        (ks ? sH2[bb][1] : sH1[bb][1]) + u };

    // ---- prologue: h1_0 = relu(xp_0 + b0); h2_{-1} = 0 -> parity 0 ----
    ull xr[3];
    {
        const ull* p = (const ull*)xb;                  // x[0] slice
        xr[0] = p[0]; xr[1] = p[1]; xr[2] = ks ? 0ull : p[2];
        ull a0 = ffma2(xw[0], xr[0], (ull)0);
        ull a1 = ffma2(xw[1], xr[1], (ull)0);
        a0 = ffma2(xw[2], xr[2], a0);
        float sA = hsum2(fadd2(a0, a1));
        float sAo = __shfl_xor_sync(0xffffffffu, sA, 16);
        if (ks == 0) {
            sH1[bb][0][u] = fmaxf(sA + sAo + bsel, 0.f);
        } else {
            sH2[bb][0][u] = 0.f;
        }
        // prefetch x[1] slice
        const ull* q = (const ull*)(xb + IN_DIM);
        xr[0] = q[0]; xr[1] = q[1]; xr[2] = ks ? 0ull : q[2];
    }
    __syncthreads();

    // ---- main loop: iter t reads parity P=t&1 (h1_t, h2_{t-1}),
    //      writes parity Q (h1_{t+1}, h2_t). One bar per step. ----
#pragma unroll 2
    for (int t = 0; t < T_STEPS; t++) {
        const int P = t & 1;
        const int Q = P ^ 1;
        const ulonglong2* r1 = h1r[P];
        const ulonglong2* r2 = h2r[P];

        // accA: w0·h1_t (k-half) + xp_{t+1} slice   -> h1_{t+1}
        // accB: wi1·h1_t + wh1·h2_{t-1} (k-half)    -> h2_t
        ull a0 = ffma2(xw[0], xr[0], (ull)0);
        ull a1 = ffma2(xw[1], xr[1], (ull)0);
        a0 = ffma2(xw[2], xr[2], a0);
        ull c0 = 0ull, c1 = 0ull;
#pragma unroll
        for (int m = 0; m < 4; m++) {
            ulonglong2 q = r1[m];          // h1_t pairs (shared by 3 uses)
            a0 = ffma2(w0h[2*m],   q.x, a0);
            a1 = ffma2(w0h[2*m+1], q.y, a1);
            c0 = ffma2(wi1h[2*m],   q.x, c0);
            c1 = ffma2(wi1h[2*m+1], q.y, c1);
        }
#pragma unroll
        for (int m = 0; m < 4; m++) {
            ulonglong2 r = r2[m];          // h2_{t-1} pairs
            c0 = ffma2(wh1h[2*m],   r.x, c0);
            c1 = ffma2(wh1h[2*m+1], r.y, c1);
        }
        float sA = hsum2(fadd2(a0, a1));
        float sB = hsum2(fadd2(c0, c1));

        // prefetch x[t+2] slice (clamped; value unused on the last iters)
        {
            const int tn = (t + 2 < T_STEPS) ? (t + 2) : (T_STEPS - 1);
            const ull* p = (const ull*)(xb + tn * IN_DIM);
            xr[0] = p[0]; xr[1] = p[1]; if (ks == 0) xr[2] = p[2];
        }

        const float sAo = __shfl_xor_sync(0xffffffffu, sA, 16);
        const float sBo = __shfl_xor_sync(0xffffffffu, sB, 16);
        // ks=0 lane publishes h1_{t+1}[u]; ks=1 lane publishes h2_t[u]
        const float vsel = ks ? (sB + sBo) : (sA + sAo);
        st[Q][0] = fmaxf(vsel + bsel, 0.f);
        __syncthreads();
    }

    // h2_511 was written at t=511 to parity (511&1)^1 = 0
    if (hb == 0 && lid < NCLS) {
        float o = bfc[lid];
        const float* wr  = Wfc + lid * 32;
        const float* h2f = sH2[bb][0];
#pragma unroll
        for (int j = 0; j < 32; j++) o += h2f[j] * wr[j];
        out[(size_t)b * NCLS + lid] = o;
    }
}

extern "C" void kernel_launch(void* const* d_in, const int* in_sizes, int n_in,
                              void* d_out, int out_size)
{
    const float* x    = (const float*)d_in[0];
    const float* Wih0 = (const float*)d_in[1];
    const float* Whh0 = (const float*)d_in[2];
    const float* bih0 = (const float*)d_in[3];
    const float* bhh0 = (const float*)d_in[4];
    const float* Wih1 = (const float*)d_in[5];
    const float* Whh1 = (const float*)d_in[6];
    const float* bih1 = (const float*)d_in[7];
    const float* bhh1 = (const float*)d_in[8];
    const float* Wfc  = (const float*)d_in[9];
    const float* bfc  = (const float*)d_in[10];
    float* out = (float*)d_out;

    rnn_fused_kernel<<<BATCH / 2, 128>>>(
        x, Wih0, Whh0, bih0, bhh0, Wih1, Whh1, bih1, bhh1, Wfc, bfc, out);
}